// round 8
// baseline (speedup 1.0000x reference)
#include <cuda_runtime.h>
#include <cuda_bf16.h>
#include <cstdint>

// VQ: HMMA screening + exact scalar rescue.
// Phase 1 (MMA): 2-split bf16 (z=zh+zl, e=eh+el, truncated), 3 term-groups
//   zh.eh + zl.eh + zh.el  -> dot error ~1e-7 absolute.
//   Track per-row best + second-best. If second > best + THRESH, the MMA
//   argmin provably equals the exact-scalar argmin (all other codes are
//   outside the ambiguity window). Emit directly.
// Phase 2 (cleanup): rows with second <= best + THRESH get a full exact
//   re-scan using the bit-identical scalar formula from the rel_err=0.0
//   kernels (4-acc f32x2 tree, d = fl(fmaf(-2,dot,z2)) + e2, tie->lowest).

#define DIMS    64
#define KA      128           // bf16 per row: [zh|zl] / [eh|el]
#define MROWS   128
#define TILE_N  128
#define NSTEP   (TILE_N / 8)
#define CTA     256
#define MAX_K   2048
#define THRESH  4e-5f

#define ASTRIDE 272           // 256B + 16B pad

__device__ float         g_e2[MAX_K];
__device__ __nv_bfloat16 g_cbB[MAX_K * KA];
__device__ int           g_flag_count;
__device__ int           g_flag_rows[65536];

// smem layout
#define OFF_E2    0            // 1024 f32
#define OFF_Z2    4096         // 128 f32
#define OFF_BIDX  4608         // 128 i32
#define OFF_A     5120         // 128*272
#define OFF_B0    39936
#define OFF_B1    74752
#define SMEM_TOTAL 109568

typedef unsigned long long u64;

__device__ __forceinline__ uint32_t smem_u32(const void* p) {
    uint32_t a;
    asm("{ .reg .u64 t; cvta.to.shared.u64 t, %1; cvt.u32.u64 %0, t; }" : "=r"(a) : "l"(p));
    return a;
}
__device__ __forceinline__ void cp16(uint32_t dst, const void* src) {
    asm volatile("cp.async.cg.shared.global [%0], [%1], 16;" :: "r"(dst), "l"(src));
}
#define CP_COMMIT() asm volatile("cp.async.commit_group;" ::: "memory")
#define CP_WAIT0()  asm volatile("cp.async.wait_group 0;" ::: "memory")
#define CP_WAIT1()  asm volatile("cp.async.wait_group 1;" ::: "memory")

__device__ __forceinline__ void ldsm_x4(uint32_t a[4], uint32_t addr) {
    asm volatile("ldmatrix.sync.aligned.m8n8.x4.shared.b16 {%0,%1,%2,%3}, [%4];"
                 : "=r"(a[0]), "=r"(a[1]), "=r"(a[2]), "=r"(a[3]) : "r"(addr));
}
__device__ __forceinline__ void mma16816(float c[4], const uint32_t a[4], const uint32_t b[2]) {
    asm volatile("mma.sync.aligned.m16n8k16.row.col.f32.bf16.bf16.f32 "
                 "{%0,%1,%2,%3}, {%4,%5,%6,%7}, {%8,%9}, {%0,%1,%2,%3};"
                 : "+f"(c[0]), "+f"(c[1]), "+f"(c[2]), "+f"(c[3])
                 : "r"(a[0]), "r"(a[1]), "r"(a[2]), "r"(a[3]), "r"(b[0]), "r"(b[1]));
}
__device__ __forceinline__ uint32_t pack_bf(__nv_bfloat16 a, __nv_bfloat16 b) {
    return (uint32_t)__bfloat16_as_ushort(a) | ((uint32_t)__bfloat16_as_ushort(b) << 16);
}
__device__ __forceinline__ void split2(float v, __nv_bfloat16& h, __nv_bfloat16& l) {
    h = __float2bfloat16_rz(v);
    l = __float2bfloat16_rz(__fsub_rn(v, __bfloat162float(h)));
}
// f32x2 helpers for the exact scalar path
__device__ __forceinline__ u64 fma2(u64 a, u64 b, u64 c) {
    u64 r; asm("fma.rn.f32x2 %0, %1, %2, %3;" : "=l"(r) : "l"(a), "l"(b), "l"(c)); return r;
}
__device__ __forceinline__ u64 add2(u64 a, u64 b) {
    u64 r; asm("add.rn.f32x2 %0, %1, %2;" : "=l"(r) : "l"(a), "l"(b)); return r;
}
__device__ __forceinline__ void unpack2(u64 v, float& lo, float& hi) {
    asm("mov.b64 {%0, %1}, %2;" : "=f"(lo), "=f"(hi) : "l"(v));
}

// ---- prep: e2 + codebook [eh|el] bf16 + flag reset ---------------------------
__global__ void prep_kernel(const float* __restrict__ cb, int K) {
    if (blockIdx.x == 0 && threadIdx.x == 0) g_flag_count = 0;
    int k = blockIdx.x * blockDim.x + threadIdx.x;
    if (k >= K) return;
    const float* row = cb + (size_t)k * DIMS;
    __nv_bfloat16* out = g_cbB + (size_t)k * KA;
    float s = 0.f;
#pragma unroll 8
    for (int d = 0; d < DIMS; d++) {
        float e = row[d];
        s = __fadd_rn(s, __fmul_rn(e, e));
        __nv_bfloat16 h, l;
        split2(e, h, l);
        out[d]        = h;
        out[DIMS + d] = l;
    }
    g_e2[k] = s;
}

// ---- main MMA kernel ----------------------------------------------------------
extern __shared__ __align__(128) char smem[];

__device__ __forceinline__ void load_b_tile(uint32_t sb, int buf, int tile,
                                            int t, int nth) {
    const uint32_t dst = sb + (buf ? OFF_B1 : OFF_B0);
    const char* src = (const char*)(g_cbB + (size_t)tile * TILE_N * KA);
    for (int p = t; p < TILE_N * 16; p += nth) {      // 128 rows x 16 16B pieces
        int r = p >> 4, c = p & 15;
        cp16(dst + r * ASTRIDE + c * 16, src + r * 256 + c * 16);
    }
}

__device__ __forceinline__ void upd(float d, int idx, float& b1, int& i1, float& b2) {
    bool lt  = d < b1;
    bool lt2 = d < b2;
    b2 = lt ? b1 : (lt2 ? d : b2);
    i1 = lt ? idx : i1;
    b1 = lt ? d   : b1;
}

__global__ __launch_bounds__(CTA, 1)
void vq_mma_kernel(const float* __restrict__ z, const float* __restrict__ cb,
                   int N, int K, float* __restrict__ out_q, float* __restrict__ out_idx)
{
    const uint32_t sb = smem_u32(smem);
    const int tid  = threadIdx.x;
    const int lane = tid & 31;
    const int wid  = tid >> 5;
    const int NTILES = K / TILE_N;

    float* s_e2 = (float*)(smem + OFF_E2);
    float* s_z2 = (float*)(smem + OFF_Z2);
    int*   s_bi = (int*)(smem + OFF_BIDX);

    for (int i = tid; i < K; i += CTA) s_e2[i] = g_e2[i];

    if (tid < 128) {
        const int row = tid;
        const int n_row = blockIdx.x * MROWS + row;
        const bool act = (n_row < N);
        const float4* zp = reinterpret_cast<const float4*>(z + (size_t)(act ? n_row : 0) * DIMS);
        char* arow = smem + OFF_A + row * ASTRIDE;
        float z2 = 0.f;
#pragma unroll
        for (int i = 0; i < DIMS / 4; i++) {
            float4 v = act ? zp[i] : make_float4(0.f, 0.f, 0.f, 0.f);
            z2 = __fadd_rn(z2, __fmul_rn(v.x, v.x));
            z2 = __fadd_rn(z2, __fmul_rn(v.y, v.y));
            z2 = __fadd_rn(z2, __fmul_rn(v.z, v.z));
            z2 = __fadd_rn(z2, __fmul_rn(v.w, v.w));
            __nv_bfloat16 hx, lx, hy, ly, hz, lz, hw, lw;
            split2(v.x, hx, lx); split2(v.y, hy, ly);
            split2(v.z, hz, lz); split2(v.w, hw, lw);
            *(uint32_t*)(arow + i * 8)           = pack_bf(hx, hy);   // zh
            *(uint32_t*)(arow + i * 8 + 4)       = pack_bf(hz, hw);
            *(uint32_t*)(arow + 128 + i * 8)     = pack_bf(lx, ly);   // zl
            *(uint32_t*)(arow + 128 + i * 8 + 4) = pack_bf(lz, lw);
        }
        s_z2[row] = z2;
    } else {
        load_b_tile(sb, 0, 0, tid - 128, 128);
        CP_COMMIT();
    }
    __syncthreads();

    // A fragments: zh chunks 0-3, zl chunks 4-7
    const int mrow = wid * 16;
    uint32_t afr[8][4];
    {
        uint32_t abase = sb + OFF_A + (mrow + (lane & 15)) * ASTRIDE + (lane >> 4) * 16;
#pragma unroll
        for (int kc = 0; kc < 8; kc++) ldsm_x4(afr[kc], abase + kc * 32);
    }
    const int r0 = mrow + (lane >> 2);
    const float z2a = s_z2[r0];
    const float z2b = s_z2[r0 + 8];

    float b1a = 3.4e38f, b2a = 3.4e38f, b1b = 3.4e38f, b2b = 3.4e38f;
    int   i1a = 0, i1b = 0;

    for (int t = 0; t < NTILES; t++) {
        if (t + 1 < NTILES) {
            load_b_tile(sb, (t + 1) & 1, t + 1, tid, CTA);
            CP_COMMIT();
            CP_WAIT1();
        } else {
            CP_WAIT0();
        }
        __syncthreads();

        const uint32_t bbase = sb + ((t & 1) ? OFF_B1 : OFF_B0)
                             + (lane & 7) * ASTRIDE + (lane >> 3) * 16;
        for (int n0 = 0; n0 < NSTEP; n0++) {
            const uint32_t baddr = bbase + n0 * 8 * ASTRIDE;
            uint32_t b[8][2];                      // eh: 0-3, el: 4-7
#pragma unroll
            for (int g = 0; g < 4; g++) {
                uint32_t q[4];
                ldsm_x4(q, baddr + g * 64);
                b[2*g][0] = q[0]; b[2*g][1] = q[1];
                b[2*g+1][0] = q[2]; b[2*g+1][1] = q[3];
            }
            float acc[4] = {0.f, 0.f, 0.f, 0.f};
#pragma unroll
            for (int kc = 0; kc < 4; kc++) {
                mma16816(acc, afr[kc + 4], b[kc]);       // zl.eh (small first)
                mma16816(acc, afr[kc],     b[kc + 4]);   // zh.el
                mma16816(acc, afr[kc],     b[kc]);       // zh.eh
            }
            const int c0 = t * TILE_N + n0 * 8 + 2 * (lane & 3);
            const float e20 = s_e2[c0], e21 = s_e2[c0 + 1];
            float d;
            d = __fadd_rn(__fmaf_rn(-2.f, acc[0], z2a), e20); upd(d, c0,     b1a, i1a, b2a);
            d = __fadd_rn(__fmaf_rn(-2.f, acc[1], z2a), e21); upd(d, c0 + 1, b1a, i1a, b2a);
            d = __fadd_rn(__fmaf_rn(-2.f, acc[2], z2b), e20); upd(d, c0,     b1b, i1b, b2b);
            d = __fadd_rn(__fmaf_rn(-2.f, acc[3], z2b), e21); upd(d, c0 + 1, b1b, i1b, b2b);
        }
        __syncthreads();
    }

    // ---- merge 4 lanes per row: (min, idx tie->low, global 2nd) --------------
#pragma unroll
    for (int delta = 1; delta <= 2; delta <<= 1) {
        float o1 = __shfl_xor_sync(0xffffffffu, b1a, delta);
        int   oi = __shfl_xor_sync(0xffffffffu, i1a, delta);
        float o2 = __shfl_xor_sync(0xffffffffu, b2a, delta);
        bool less = (o1 < b1a) || (o1 == b1a && oi < i1a);
        float loser = less ? b1a : o1;
        b1a = less ? o1 : b1a;
        i1a = less ? oi : i1a;
        b2a = fminf(fminf(b2a, o2), loser);

        o1 = __shfl_xor_sync(0xffffffffu, b1b, delta);
        oi = __shfl_xor_sync(0xffffffffu, i1b, delta);
        o2 = __shfl_xor_sync(0xffffffffu, b2b, delta);
        less = (o1 < b1b) || (o1 == b1b && oi < i1b);
        loser = less ? b1b : o1;
        b1b = less ? o1 : b1b;
        i1b = less ? oi : i1b;
        b2b = fminf(fminf(b2b, o2), loser);
    }

    if ((lane & 3) == 0) {
        s_bi[r0]     = i1a;
        s_bi[r0 + 8] = i1b;
        const int na = blockIdx.x * MROWS + r0;
        const int nb = na + 8;
        if (na < N && b2a <= b1a + THRESH) {
            int p = atomicAdd(&g_flag_count, 1);
            g_flag_rows[p] = na;
        }
        if (nb < N && b2b <= b1b + THRESH) {
            int p = atomicAdd(&g_flag_count, 1);
            g_flag_rows[p] = nb;
        }
    }
    __syncthreads();

    if (tid < 128) {
        const int n_row = blockIdx.x * MROWS + tid;
        if (n_row < N) {
            const int bi = s_bi[tid];
            const float4* crow = reinterpret_cast<const float4*>(cb + (size_t)bi * DIMS);
            float4* orow = reinterpret_cast<float4*>(out_q + (size_t)n_row * DIMS);
#pragma unroll
            for (int i = 0; i < DIMS / 4; i++) orow[i] = crow[i];
            if (out_idx) out_idx[n_row] = (float)bi;
        }
    }
}

// ---- cleanup: exact scalar re-scan for flagged rows (R1-identical math) -------
__global__ __launch_bounds__(256, 4)
void cleanup_kernel(const float* __restrict__ z, const float* __restrict__ cb,
                    int K, float* __restrict__ out_q, float* __restrict__ out_idx)
{
    const int nflag = g_flag_count;
    const int lane = threadIdx.x & 31;
    const int warps = gridDim.x * (blockDim.x >> 5);
    const int w = blockIdx.x * (blockDim.x >> 5) + (threadIdx.x >> 5);

    for (int f = w; f < nflag; f += warps) {
        const int row = g_flag_rows[f];
        // z row -> packed f32x2, z2 in reference order
        u64 zr[DIMS / 2];
        float z2 = 0.f;
        const ulonglong2* zp = reinterpret_cast<const ulonglong2*>(z + (size_t)row * DIMS);
#pragma unroll
        for (int i = 0; i < DIMS / 4; i++) {
            ulonglong2 a = zp[i];
            zr[2 * i] = a.x; zr[2 * i + 1] = a.y;
            float x, y;
            unpack2(a.x, x, y);
            z2 = __fadd_rn(z2, __fmul_rn(x, x)); z2 = __fadd_rn(z2, __fmul_rn(y, y));
            unpack2(a.y, x, y);
            z2 = __fadd_rn(z2, __fmul_rn(x, x)); z2 = __fadd_rn(z2, __fmul_rn(y, y));
        }
        float best = 3.4e38f;
        int   bidx = 0x7fffffff;
        for (int k = lane; k < K; k += 32) {
            const ulonglong2* cs = reinterpret_cast<const ulonglong2*>(cb + (size_t)k * DIMS);
            u64 a0 = 0, a1 = 0, a2 = 0, a3 = 0;
#pragma unroll
            for (int j = 0; j < DIMS / 8; j++) {
                ulonglong2 c0 = cs[2 * j], c1 = cs[2 * j + 1];
                a0 = fma2(zr[4 * j + 0], c0.x, a0);
                a1 = fma2(zr[4 * j + 1], c0.y, a1);
                a2 = fma2(zr[4 * j + 2], c1.x, a2);
                a3 = fma2(zr[4 * j + 3], c1.y, a3);
            }
            u64 s = add2(add2(a0, a1), add2(a2, a3));
            float lo, hi; unpack2(s, lo, hi);
            float dot = __fadd_rn(lo, hi);
            float d = __fadd_rn(__fmaf_rn(-2.f, dot, z2), g_e2[k]);
            if (d < best) { best = d; bidx = k; }
        }
#pragma unroll
        for (int delta = 16; delta; delta >>= 1) {
            float ob = __shfl_xor_sync(0xffffffffu, best, delta);
            int   oi = __shfl_xor_sync(0xffffffffu, bidx, delta);
            bool tk = (ob < best) || (ob == best && oi < bidx);
            best = tk ? ob : best;
            bidx = tk ? oi : bidx;
        }
        // rewrite outputs
        const float2* crow = reinterpret_cast<const float2*>(cb + (size_t)bidx * DIMS);
        float2* orow = reinterpret_cast<float2*>(out_q + (size_t)row * DIMS);
        orow[lane] = crow[lane];
        if (lane == 0 && out_idx) out_idx[row] = (float)bidx;
    }
}

extern "C" void kernel_launch(void* const* d_in, const int* in_sizes, int n_in,
                              void* d_out, int out_size) {
    const float* z  = (const float*)d_in[0];
    const float* cb = (const float*)d_in[1];
    const int N = in_sizes[0] / DIMS;
    const int K = in_sizes[1] / DIMS;
    float* out = (float*)d_out;

    float* out_idx = nullptr;
    if ((long long)out_size >= (long long)N * DIMS + N)
        out_idx = out + (size_t)N * DIMS;

    cudaFuncSetAttribute(vq_mma_kernel, cudaFuncAttributeMaxDynamicSharedMemorySize, SMEM_TOTAL);

    prep_kernel<<<(K + 127) / 128, 128>>>(cb, K);
    vq_mma_kernel<<<(N + MROWS - 1) / MROWS, CTA, SMEM_TOTAL>>>(z, cb, N, K, out, out_idx);
    cleanup_kernel<<<64, 256>>>(z, cb, K, out, out_idx);
}

// round 9
// speedup vs baseline: 1.6510x; 1.6510x over previous
#include <cuda_runtime.h>
#include <cstdint>

// VQ: argmin_k ||z_n - e_k||^2 -> z_q + indices. Pure scalar FFMA2 path
// (mma.sync measured at ~FFMA rate on sm_103 via compute_103 PTX; tensor
// path abandoned). R9 vs R3 (230us, fma=52.9%, issue=45%, grid=128):
//   - CTA=128, RPT=2 -> grid=256, 2 CTAs/SM resident -> single wave, 4 w/SMSP
//   - epilogue packed to f32x2 across the 2 rows (bit-identical per lane)
// Numerics byte-exact vs the rel_err=0.0 kernels (4-acc tree, unfused z2/e2,
// d = fl(fmaf(-2,dot,z2)) + e2, tie keeps lowest index).

#define DIMS 64
#define TK   128     // codes per smem tile
#define CTA  128
#define RPT  2       // rows per thread

__device__ float g_e2[8192];

typedef unsigned long long u64;

__device__ __forceinline__ u64 fma2(u64 a, u64 b, u64 c) {
    u64 r;
    asm("fma.rn.f32x2 %0, %1, %2, %3;" : "=l"(r) : "l"(a), "l"(b), "l"(c));
    return r;
}
__device__ __forceinline__ u64 add2(u64 a, u64 b) {
    u64 r;
    asm("add.rn.f32x2 %0, %1, %2;" : "=l"(r) : "l"(a), "l"(b));
    return r;
}
__device__ __forceinline__ void unpack2(u64 v, float& lo, float& hi) {
    asm("mov.b64 {%0, %1}, %2;" : "=f"(lo), "=f"(hi) : "l"(v));
}
__device__ __forceinline__ u64 pack2(float lo, float hi) {
    u64 r;
    asm("mov.b64 %0, {%1, %2};" : "=l"(r) : "f"(lo), "f"(hi));
    return r;
}

// ---- pass 1: ||e_k||^2 (reference order: square then add) --------------------
__global__ void e2_kernel(const float* __restrict__ cb, int K) {
    int k = blockIdx.x * blockDim.x + threadIdx.x;
    if (k >= K) return;
    const float4* row = reinterpret_cast<const float4*>(cb + (size_t)k * DIMS);
    float s = 0.f;
#pragma unroll
    for (int i = 0; i < DIMS / 4; i++) {
        float4 v = row[i];
        s = __fadd_rn(s, __fmul_rn(v.x, v.x));
        s = __fadd_rn(s, __fmul_rn(v.y, v.y));
        s = __fadd_rn(s, __fmul_rn(v.z, v.z));
        s = __fadd_rn(s, __fmul_rn(v.w, v.w));
    }
    g_e2[k] = s;
}

// ---- pass 2: main VQ ----------------------------------------------------------
__global__ __launch_bounds__(CTA, 2)
void vq_kernel(const float* __restrict__ z, const float* __restrict__ cb,
               int N, int K, float* __restrict__ out_q, float* __restrict__ out_idx)
{
    __shared__ float s_tile[TK * DIMS];
    __shared__ float s_e2[TK];

    const int n0 = blockIdx.x * (CTA * RPT) + threadIdx.x;
    const int n1 = n0 + CTA;
    const bool act0 = (n0 < N);
    const bool act1 = (n1 < N);

    // z rows in packed f32x2 registers (+ unfused ||z||^2, reference order)
    u64 zr0[DIMS / 2], zr1[DIMS / 2];
    float z20 = 0.f, z21 = 0.f;
    {
        const ulonglong2* zp0 = reinterpret_cast<const ulonglong2*>(z + (size_t)(act0 ? n0 : 0) * DIMS);
        const ulonglong2* zp1 = reinterpret_cast<const ulonglong2*>(z + (size_t)(act1 ? n1 : 0) * DIMS);
#pragma unroll
        for (int i = 0; i < DIMS / 4; i++) {
            ulonglong2 a = zp0[i];
            ulonglong2 b = zp1[i];
            zr0[2 * i + 0] = a.x; zr0[2 * i + 1] = a.y;
            zr1[2 * i + 0] = b.x; zr1[2 * i + 1] = b.y;
            float x, y;
            unpack2(a.x, x, y); z20 = __fadd_rn(z20, __fmul_rn(x, x)); z20 = __fadd_rn(z20, __fmul_rn(y, y));
            unpack2(a.y, x, y); z20 = __fadd_rn(z20, __fmul_rn(x, x)); z20 = __fadd_rn(z20, __fmul_rn(y, y));
            unpack2(b.x, x, y); z21 = __fadd_rn(z21, __fmul_rn(x, x)); z21 = __fadd_rn(z21, __fmul_rn(y, y));
            unpack2(b.y, x, y); z21 = __fadd_rn(z21, __fmul_rn(x, x)); z21 = __fadd_rn(z21, __fmul_rn(y, y));
        }
    }
    const u64 z2pair  = pack2(z20, z21);
    const u64 neg2pair = pack2(-2.f, -2.f);

    float best0 = 3.4e38f, best1 = 3.4e38f;
    int   bidx0 = 0,       bidx1 = 0;

    for (int t0 = 0; t0 < K; t0 += TK) {
        __syncthreads();
        {   // stage codebook tile (coalesced float4) + e2 slice
            const float4* cp = reinterpret_cast<const float4*>(cb + (size_t)t0 * DIMS);
            float4* sp = reinterpret_cast<float4*>(s_tile);
#pragma unroll 4
            for (int i = threadIdx.x; i < TK * DIMS / 4; i += CTA) sp[i] = cp[i];
            s_e2[threadIdx.x] = g_e2[t0 + threadIdx.x];
        }
        __syncthreads();

#pragma unroll 2
        for (int kk = 0; kk < TK; kk++) {
            const ulonglong2* cs =
                reinterpret_cast<const ulonglong2*>(s_tile + kk * DIMS);
            const float e2  = s_e2[kk];
            const int  kidx = t0 + kk;

            u64 a0 = 0, a1 = 0, a2 = 0, a3 = 0;   // row0: 4-acc tree (as R1)
            u64 b0 = 0, b1 = 0, b2 = 0, b3 = 0;   // row1
#pragma unroll
            for (int j = 0; j < DIMS / 8; j++) {
                ulonglong2 c0 = cs[2 * j + 0];
                ulonglong2 c1 = cs[2 * j + 1];
                a0 = fma2(zr0[4 * j + 0], c0.x, a0);
                a1 = fma2(zr0[4 * j + 1], c0.y, a1);
                a2 = fma2(zr0[4 * j + 2], c1.x, a2);
                a3 = fma2(zr0[4 * j + 3], c1.y, a3);
                b0 = fma2(zr1[4 * j + 0], c0.x, b0);
                b1 = fma2(zr1[4 * j + 1], c0.y, b1);
                b2 = fma2(zr1[4 * j + 2], c1.x, b2);
                b3 = fma2(zr1[4 * j + 3], c1.y, b3);
            }
            // packed epilogue: each lane bit-identical to
            //   dot = fadd(lo,hi); d = fadd(fmaf(-2,dot,z2), e2)
            u64 sa = add2(add2(a0, a1), add2(a2, a3));
            u64 sb = add2(add2(b0, b1), add2(b2, b3));
            float al, ah, bl, bh;
            unpack2(sa, al, ah);
            unpack2(sb, bl, bh);
            u64 dot2 = add2(pack2(al, bl), pack2(ah, bh));   // (dot0, dot1)
            u64 tt   = fma2(neg2pair, dot2, z2pair);          // z2 - 2*dot
            u64 dd   = add2(tt, pack2(e2, e2));               // + e2
            float d0, d1;
            unpack2(dd, d0, d1);
            bool lt0 = d0 < best0;
            best0 = lt0 ? d0   : best0;
            bidx0 = lt0 ? kidx : bidx0;
            bool lt1 = d1 < best1;
            best1 = lt1 ? d1   : best1;
            bidx1 = lt1 ? kidx : bidx1;
        }
    }

    if (act0) {
        const float4* crow = reinterpret_cast<const float4*>(cb + (size_t)bidx0 * DIMS);
        float4* orow = reinterpret_cast<float4*>(out_q + (size_t)n0 * DIMS);
#pragma unroll
        for (int i = 0; i < DIMS / 4; i++) orow[i] = crow[i];
        if (out_idx) out_idx[n0] = (float)bidx0;
    }
    if (act1) {
        const float4* crow = reinterpret_cast<const float4*>(cb + (size_t)bidx1 * DIMS);
        float4* orow = reinterpret_cast<float4*>(out_q + (size_t)n1 * DIMS);
#pragma unroll
        for (int i = 0; i < DIMS / 4; i++) orow[i] = crow[i];
        if (out_idx) out_idx[n1] = (float)bidx1;
    }
}

extern "C" void kernel_launch(void* const* d_in, const int* in_sizes, int n_in,
                              void* d_out, int out_size) {
    const float* z  = (const float*)d_in[0];
    const float* cb = (const float*)d_in[1];
    const int N = in_sizes[0] / DIMS;
    const int K = in_sizes[1] / DIMS;
    float* out = (float*)d_out;

    float* out_idx = nullptr;
    if ((long long)out_size >= (long long)N * DIMS + N)
        out_idx = out + (size_t)N * DIMS;

    e2_kernel<<<(K + 255) / 256, 256>>>(cb, K);
    const int rows_per_block = CTA * RPT;
    vq_kernel<<<(N + rows_per_block - 1) / rows_per_block, CTA>>>(z, cb, N, K, out, out_idx);
}